// round 16
// baseline (speedup 1.0000x reference)
#include <cuda_runtime.h>
#include <math.h>

#define D    4096
#define H    64
#define S    64
#define EPSF 1e-5f
#define NBLK 592
#define NTHR 256
#define TILE_B 16384u               // one weight row = 16 KB

// Scratch (allocation-free rule: __device__ globals)
__device__ __align__(16) float g_mix[4 * D];   // [r, k, v, g] mixed vectors
__device__ __align__(16) float g_rkvg[4 * D];  // [r, k, v, g] matvec results
__device__ __align__(16) float g_y[D];         // gated normalized wkv
__device__ unsigned g_count = 0;  // grid barrier arrival counter
__device__ unsigned g_gen   = 0;  // grid barrier generation

// ---------------------------------------------------------------------------
// PTX helpers
// ---------------------------------------------------------------------------
__device__ __forceinline__ unsigned smem_u32(const void* p)
{
    unsigned a;
    asm("{ .reg .u64 t; cvta.to.shared.u64 t, %1; cvt.u32.u64 %0, t; }"
        : "=r"(a) : "l"(p));
    return a;
}

#define MBAR_INIT(addr, cnt) \
    asm volatile("mbarrier.init.shared.b64 [%0], %1;" :: "r"(addr), "r"(cnt) : "memory")

#define MBAR_TX(addr, bytes) \
    asm volatile("mbarrier.arrive.expect_tx.shared.b64 _, [%0], %1;" \
                 :: "r"(addr), "r"(bytes) : "memory")

#define TMA_G2S(dst, src, bytes, mbar) \
    asm volatile("cp.async.bulk.shared::cluster.global.mbarrier::complete_tx::bytes " \
                 "[%0], [%1], %2, [%3];" \
                 :: "r"(dst), "l"(src), "r"(bytes), "r"(mbar) : "memory")

#define MBAR_WAIT(addr, ph) do {                                              \
    asm volatile("{\n\t.reg .pred p;\n\t"                                     \
                 "W_%=:\n\t"                                                  \
                 "mbarrier.try_wait.parity.acquire.cta.shared::cta.b64 p, [%0], %1, 0x989680;\n\t" \
                 "@!p bra W_%=;\n\t}"                                         \
                 :: "r"(addr), "r"(ph) : "memory");                           \
} while (0)

#define FENCE_ASYNC() \
    asm volatile("fence.proxy.async.shared::cta;" ::: "memory")

// ---------------------------------------------------------------------------
// Grid-wide barrier for a fully co-resident persistent grid.
// ---------------------------------------------------------------------------
__device__ __forceinline__ void grid_barrier()
{
    __syncthreads();
    if (threadIdx.x == 0) {
        __threadfence();
        unsigned gen = *(volatile unsigned*)&g_gen;
        if (atomicAdd(&g_count, 1) == NBLK - 1) {
            g_count = 0;
            __threadfence();
            atomicExch(&g_gen, gen + 1);
        } else {
            while (*(volatile unsigned*)&g_gen == gen) { }
            __threadfence();
        }
    }
    __syncthreads();
}

// ---------------------------------------------------------------------------
// Fused persistent kernel. 592 blocks x 256 threads, all co-resident.
// Weight stream: 3-buffer TMA ring, depth-2 prefetch, unified task list
// (phase-2 tasks 0..n2-1 = Wr/Wk/Wv/Wg rows; then n4 Wo rows).
// ---------------------------------------------------------------------------
__global__ __launch_bounds__(NTHR, 4) void rwkv_fused(
    const float* __restrict__ x,     const float* __restrict__ state1,
    const float* __restrict__ state2,
    const float* __restrict__ tmk,   const float* __restrict__ tmv,
    const float* __restrict__ tmr,   const float* __restrict__ tmg,
    const float* __restrict__ tdec,  const float* __restrict__ tfir,
    const float* __restrict__ Wr,    const float* __restrict__ Wk,
    const float* __restrict__ Wv,    const float* __restrict__ Wg,
    const float* __restrict__ Wo,
    const float* __restrict__ ln1w,  const float* __restrict__ ln1b,
    const float* __restrict__ lnxw,  const float* __restrict__ lnxb,
    float* __restrict__ out, float* __restrict__ state1_out,
    float* __restrict__ state2_out)
{
    extern __shared__ __align__(128) float wbuf[];       // 3 x 4096 floats
    __shared__ __align__(16)  float pw[16][S];           // float4-accessed
    __shared__ __align__(8) unsigned long long mbar_s[3];
    __shared__ float part[2][8];
    __shared__ float ra[8], rb[8];
    __shared__ float s_mean, s_rstd;
    __shared__ float sk[S], sr[S], stf[S], sdec[S], sw[S];

    const int tid = threadIdx.x, bid = blockIdx.x;
    const int warp = tid >> 5, lane = tid & 31;
    const unsigned mbb   = smem_u32(&mbar_s[0]);
    const unsigned wbase = smem_u32(wbuf);

    // Per-block task counts (strided by NBLK, remainder-guarded)
    const int n2 = (16384 - bid + NBLK - 1) / NBLK;   // 27 or 28
    const int n4 = (4096  - bid + NBLK - 1) / NBLK;   // 6 or 7
    const int n  = n2 + n4;

    // src address of unified task u
    auto task_src = [&](int u) -> const float* {
        if (u < n2) {
            int t = bid + NBLK * u;
            int m = t >> 12, row = t & 4095;
            const float* W = (m == 0) ? Wr : (m == 1) ? Wk
                           : (m == 2) ? Wv : Wg;
            return W + (size_t)row * D;
        }
        int t4 = bid + NBLK * (u - n2);
        return Wo + (size_t)t4 * D;
    };

    if (tid == 0) {
        MBAR_INIT(mbb + 0, 1);
        MBAR_INIT(mbb + 8, 1);
        MBAR_INIT(mbb + 16, 1);
        FENCE_ASYNC();
        // depth-2 prologue: tasks 0, 1 (Wr rows — independent of LN)
        MBAR_TX(mbb + 0, TILE_B);
        TMA_G2S(wbase + 0 * TILE_B, task_src(0), TILE_B, mbb + 0);
        MBAR_TX(mbb + 8, TILE_B);
        TMA_G2S(wbase + 1 * TILE_B, task_src(1), TILE_B, mbb + 8);
    }
    __syncthreads();
    int u = 2;

    // ---------------- Phase 1: LN + 4 token-mixes (blocks 0..63) ------------
    if (bid < 64) {
        float s = 0.f, sq = 0.f;
#pragma unroll
        for (int k = 0; k < 4; k++) {
            float4 v = ((const float4*)x)[tid + k * 256];
            s  += v.x + v.y + v.z + v.w;
            sq += v.x * v.x + v.y * v.y + v.z * v.z + v.w * v.w;
        }
#pragma unroll
        for (int o = 16; o; o >>= 1) {
            s  += __shfl_xor_sync(0xffffffffu, s, o);
            sq += __shfl_xor_sync(0xffffffffu, sq, o);
        }
        if (lane == 0) { ra[warp] = s; rb[warp] = sq; }
        __syncthreads();
        if (tid == 0) {
            float ts = 0.f, tq = 0.f;
#pragma unroll
            for (int i = 0; i < 8; i++) { ts += ra[i]; tq += rb[i]; }
            float m   = ts * (1.0f / D);
            float var = tq * (1.0f / D) - m * m;
            s_mean = m;
            s_rstd = rsqrtf(var + EPSF);
        }
        __syncthreads();
        if (tid < 64) {
            int idx = bid * 64 + tid;
            float m = s_mean, rstd = s_rstd;
            float xi = x[idx];
            float xx = (xi - m) * rstd * ln1w[idx] + ln1b[idx];
            state1_out[idx] = xx;
            float st = state1[idx];
            float tr = tmr[idx], tk = tmk[idx], tv = tmv[idx], tg = tmg[idx];
            g_mix[0 * D + idx] = st * (1.f - tr) + xx * tr;
            g_mix[1 * D + idx] = st * (1.f - tk) + xx * tk;
            g_mix[2 * D + idx] = st * (1.f - tv) + xx * tv;
            g_mix[3 * D + idx] = st * (1.f - tg) + xx * tg;
        }
    }
    grid_barrier();

    // ---------------- Phase 2: 16384-row matvec (Wr,Wk,Wv,Wg) --------------
#pragma unroll 1
    for (int j = 0; j < n2; j++) {
        if (u < n) {
            if (tid == 0) {
                int b2 = u % 3;
                FENCE_ASYNC();
                MBAR_TX(mbb + b2 * 8, TILE_B);
                TMA_G2S(wbase + (unsigned)b2 * TILE_B, task_src(u), TILE_B,
                        mbb + b2 * 8);
            }
            u++;
        }
        int t = bid + NBLK * j;
        int m = t >> 12, row = t & 4095;
        const float* xp = g_mix + (m << 12) + warp * 512 + lane * 4;
        float4 x0 = *(const float4*)(xp + 0 * 128);
        float4 x1 = *(const float4*)(xp + 1 * 128);
        float4 x2 = *(const float4*)(xp + 2 * 128);
        float4 x3 = *(const float4*)(xp + 3 * 128);

        int b = j % 3;
        unsigned ph = (unsigned)(j / 3) & 1u;
        MBAR_WAIT(mbb + b * 8, ph);

        const float* wp = wbuf + b * D + warp * 512 + lane * 4;
        float4 w0 = *(const float4*)(wp + 0 * 128);
        float4 w1 = *(const float4*)(wp + 1 * 128);
        float4 w2 = *(const float4*)(wp + 2 * 128);
        float4 w3 = *(const float4*)(wp + 3 * 128);

        float a0 = w0.x * x0.x + w0.y * x0.y + w0.z * x0.z + w0.w * x0.w;
        float a1 = w1.x * x1.x + w1.y * x1.y + w1.z * x1.z + w1.w * x1.w;
        float a2 = w2.x * x2.x + w2.y * x2.y + w2.z * x2.z + w2.w * x2.w;
        float a3 = w3.x * x3.x + w3.y * x3.y + w3.z * x3.z + w3.w * x3.w;
        float acc = (a0 + a1) + (a2 + a3);
#pragma unroll
        for (int o = 16; o; o >>= 1) acc += __shfl_xor_sync(0xffffffffu, acc, o);

        if (lane == 0) part[j & 1][warp] = acc;
        __syncthreads();
        if (tid == 0) {
            const float* p = part[j & 1];
            g_rkvg[(m << 12) + row] = ((p[0] + p[1]) + (p[2] + p[3]))
                                    + ((p[4] + p[5]) + (p[6] + p[7]));
        }
    }
    // Two Wo tiles (tasks n2, n2+1) are already in flight here.

    // wkv inputs: prefetch this block's state2 tile while others finish.
    const int jg = tid & 15, ig = tid >> 4;
    float4 s2v[4];
    if (bid < 64) {
        const float4* S2 = (const float4*)(state2 + (size_t)bid * S * S);
#pragma unroll
        for (int di = 0; di < 4; di++)
            s2v[di] = S2[(ig * 4 + di) * 16 + jg];
    }
    grid_barrier();

    // ---------------- Phase 3: wkv + InstanceNorm + SiLU (blocks 0..63) ----
    if (bid < 64) {
        int h = bid;
        float4* S2o = (float4*)(state2_out + (size_t)h * S * S);
        if (tid < S) {
            sr[tid]   = g_rkvg[0 * D + h * S + tid];
            sk[tid]   = g_rkvg[1 * D + h * S + tid];
            stf[tid]  = tfir[h * S + tid];
            sdec[tid] = tdec[h * S + tid];
        }
        float4 vj = ((const float4*)(g_rkvg + 2 * D + h * S))[jg];
        __syncthreads();

        float4 acc = make_float4(0.f, 0.f, 0.f, 0.f);
#pragma unroll
        for (int di = 0; di < 4; di++) {
            int i = ig * 4 + di;
            float ki = sk[i], ri = sr[i], tfi = stf[i], dci = sdec[i];
            float4 s2 = s2v[di];
            float4 kv = make_float4(ki * vj.x, ki * vj.y, ki * vj.z, ki * vj.w);
            float4 so;
            so.x = kv.x + s2.x * dci; so.y = kv.y + s2.y * dci;
            so.z = kv.z + s2.z * dci; so.w = kv.w + s2.w * dci;
            S2o[i * 16 + jg] = so;
            acc.x += ri * (kv.x * tfi + s2.x);
            acc.y += ri * (kv.y * tfi + s2.y);
            acc.z += ri * (kv.z * tfi + s2.z);
            acc.w += ri * (kv.w * tfi + s2.w);
        }
        ((float4*)&pw[ig][0])[jg] = acc;
        __syncthreads();

        if (tid < S) {
            float wsum = 0.f;
#pragma unroll
            for (int g2 = 0; g2 < 16; g2++) wsum += pw[g2][tid];
            sw[tid] = wsum;
        }
        __syncthreads();
        if (tid < S) {
            float s = 0.f, sq = 0.f;
#pragma unroll
            for (int i = 0; i < S; i++) { float u2 = sw[i]; s += u2; sq += u2 * u2; }
            float mu  = s * (1.0f / S);
            float var = sq * (1.0f / S) - mu * mu;
            float xn  = (sw[tid] - mu) * rsqrtf(var + EPSF);
            float g    = g_rkvg[3 * D + h * S + tid];
            float gate = g / (1.f + expf(-g));   // SiLU
            g_y[h * S + tid] = (xn * lnxw[h * S + tid] + lnxb[h * S + tid]) * gate;
        }
    }
    grid_barrier();

    // ---------------- Phase 4: out = x + Wo @ y ------------------------------
    const float* yp = g_y + warp * 512 + lane * 4;
    float4 y0 = *(const float4*)(yp + 0 * 128);
    float4 y1 = *(const float4*)(yp + 1 * 128);
    float4 y2 = *(const float4*)(yp + 2 * 128);
    float4 y3 = *(const float4*)(yp + 3 * 128);

#pragma unroll 1
    for (int j = n2; j < n; j++) {
        if (u < n) {
            if (tid == 0) {
                int b2 = u % 3;
                FENCE_ASYNC();
                MBAR_TX(mbb + b2 * 8, TILE_B);
                TMA_G2S(wbase + (unsigned)b2 * TILE_B, task_src(u), TILE_B,
                        mbb + b2 * 8);
            }
            u++;
        }
        int row = bid + NBLK * (j - n2);

        int b = j % 3;
        unsigned ph = (unsigned)(j / 3) & 1u;
        MBAR_WAIT(mbb + b * 8, ph);

        const float* wp = wbuf + b * D + warp * 512 + lane * 4;
        float4 w0 = *(const float4*)(wp + 0 * 128);
        float4 w1 = *(const float4*)(wp + 1 * 128);
        float4 w2 = *(const float4*)(wp + 2 * 128);
        float4 w3 = *(const float4*)(wp + 3 * 128);

        float a0 = w0.x * y0.x + w0.y * y0.y + w0.z * y0.z + w0.w * y0.w;
        float a1 = w1.x * y1.x + w1.y * y1.y + w1.z * y1.z + w1.w * y1.w;
        float a2 = w2.x * y2.x + w2.y * y2.y + w2.z * y2.z + w2.w * y2.w;
        float a3 = w3.x * y3.x + w3.y * y3.y + w3.z * y3.z + w3.w * y3.w;
        float acc = (a0 + a1) + (a2 + a3);
#pragma unroll
        for (int o = 16; o; o >>= 1) acc += __shfl_xor_sync(0xffffffffu, acc, o);

        if (lane == 0) part[j & 1][warp] = acc;
        __syncthreads();
        if (tid == 0) {
            const float* p = part[j & 1];
            float r = ((p[0] + p[1]) + (p[2] + p[3]))
                    + ((p[4] + p[5]) + (p[6] + p[7]));
            out[row] = x[row] + r;
        }
    }
}

// ---------------------------------------------------------------------------
extern "C" void kernel_launch(void* const* d_in, const int* in_sizes, int n_in,
                              void* d_out, int out_size)
{
    const float* x      = (const float*)d_in[0];
    const float* state1 = (const float*)d_in[1];
    const float* state2 = (const float*)d_in[2];
    const float* tmk    = (const float*)d_in[3];
    const float* tmv    = (const float*)d_in[4];
    const float* tmr    = (const float*)d_in[5];
    const float* tmg    = (const float*)d_in[6];
    const float* tdec   = (const float*)d_in[7];
    const float* tfir   = (const float*)d_in[8];
    const float* Wr     = (const float*)d_in[9];
    const float* Wk     = (const float*)d_in[10];
    const float* Wv     = (const float*)d_in[11];
    const float* Wg     = (const float*)d_in[12];
    const float* Wo     = (const float*)d_in[13];
    const float* ln1w   = (const float*)d_in[14];
    const float* ln1b   = (const float*)d_in[15];
    const float* lnxw   = (const float*)d_in[16];
    const float* lnxb   = (const float*)d_in[17];

    float* out        = (float*)d_out;         // [0, D)
    float* state1_out = out + D;               // [D, 2D)
    float* state2_out = out + 2 * D;           // [2D, 2D + H*S*S)

    static const int smem_bytes = 3 * 16384;   // 48 KB dynamic (3 TMA buffers)
    cudaFuncSetAttribute(rwkv_fused,
                         cudaFuncAttributeMaxDynamicSharedMemorySize,
                         smem_bytes);

    rwkv_fused<<<NBLK, NTHR, smem_bytes>>>(x, state1, state2, tmk, tmv, tmr,
                                           tmg, tdec, tfir, Wr, Wk, Wv, Wg, Wo,
                                           ln1w, ln1b, lnxw, lnxb,
                                           out, state1_out, state2_out);
}